// round 6
// baseline (speedup 1.0000x reference)
#include <cuda_runtime.h>
#include <math.h>

// ---------------- problem constants ----------------
#define NB   64        // batch
#define NN_  200       // nodes
#define NU   64        // rnn units
#define NL   4         // layers
#define NT   12        // input_len == output_len
#define F0   264       // layer-0 features (200 + 64)
#define F1   128       // layer>0 features (64 + 64)
#define BF0  (F0*NB)   // 16896
#define BF1  (F1*NB)   // 8192
#define SEG0 (NN_*BF0) // 3,379,200
#define NNSQ 40000     // N*N
#define HSZ  (NN_*NU*NB)   // 819200, hidden layout [n][u][b]

typedef unsigned long long ull;

// ---------------- scratch (device globals; no allocation allowed) ----------
__device__ float g_Xd[2*SEG0];         // diffusion results [X1 ; X2] as rows m=0..399
__device__ float g_SS[400*200];        // [S ; 2S^2 - I]
__device__ float g_h[NL][HSZ];         // hidden per layer, [n][u][b]
__device__ float g_xin[NN_*200*64];    // layer-0 input, [n][f][b]
__device__ float g_rh[HSZ];            // r * h, [n][u][b]
__device__ float g_u[HSZ];             // update gate, [n][u][b]
__device__ float g_W[746496];          // reordered weights [k][f][o] per (side,layer,g/c)

// ---------------- f32x2 helpers ----------------
__device__ __forceinline__ ull pack2(float lo, float hi) {
    ull r; asm("mov.b64 %0,{%1,%2};" : "=l"(r) : "f"(lo), "f"(hi)); return r;
}
__device__ __forceinline__ ull ffma2(ull a, ull b, ull c) {
    ull d; asm("fma.rn.f32x2 %0,%1,%2,%3;" : "=l"(d) : "l"(a), "l"(b), "l"(c)); return d;
}
__device__ __forceinline__ float2 upk(ull v) {
    float2 f; asm("mov.b64 {%0,%1},%2;" : "=f"(f.x), "=f"(f.y) : "l"(v)); return f;
}

// ---------------- setup kernels ----------------
// SS[0:200] = S ; SS[200:400] = 2*S@S - I
__global__ void build_SS(const float* __restrict__ S) {
    int m = blockIdx.x;
    int k = threadIdx.x;
    if (k >= 200) return;
    if (m < 200) { g_SS[m*200 + k] = S[m*200 + k]; return; }
    int r = m - 200;
    float acc = 0.f;
    for (int j = 0; j < 200; j++) acc += S[r*200 + j] * S[j*200 + k];
    g_SS[m*200 + k] = 2.f*acc - (r == k ? 1.f : 0.f);
}

// src rows are (f*3+k); dst is [k][f][o] contiguous
__global__ void reorder_W(const float* __restrict__ src, int dstOff, int F, int O) {
    int idx = blockIdx.x * blockDim.x + threadIdx.x;
    int tot = 3 * F * O;
    if (idx >= tot) return;
    int k   = idx / (F * O);
    int rem = idx - k * F * O;
    int f   = rem / O;
    int o   = rem - f * O;
    g_W[dstOff + idx] = src[(f*3 + k)*O + o];
}

__global__ void zero_h() {
    int idx = blockIdx.x * blockDim.x + threadIdx.x;
    if (idx < NL*HSZ) ((float*)g_h)[idx] = 0.f;
}

// ---------------- pack: layer-0 input transpose --------------------------
// src[b*strideB + n*200 + f] -> g_xin[n][f][b] ; src==nullptr -> zeros
__global__ void pack_l0_input(const float* __restrict__ src, int strideB) {
    __shared__ float s[32][33];
    int n  = blockIdx.x;
    int f0 = blockIdx.y * 32;
    int b0 = blockIdx.z * 32;
    int tx = threadIdx.x, ty = threadIdx.y;     // 32 x 8
    if (src) {
        #pragma unroll
        for (int i = 0; i < 4; i++) {
            int b = b0 + ty + 8*i;
            int f = f0 + tx;
            s[ty + 8*i][tx] = (f < 200) ? src[b*strideB + n*200 + f] : 0.f;
        }
    } else {
        #pragma unroll
        for (int i = 0; i < 4; i++) s[ty + 8*i][tx] = 0.f;
    }
    __syncthreads();
    #pragma unroll
    for (int i = 0; i < 4; i++) {
        int f = f0 + ty + 8*i;
        if (f < 200) g_xin[n*12800 + f*64 + b0 + tx] = s[tx][ty + 8*i];
    }
}

// ---------------- GEMM 1: Y(400 x cols) = SS(400x200) @ X0(200 x cols) ----
// X0 is virtual: col=(f*64+b); col<split -> src0[m*st0+col]; else src1[m*4096+col-split]
// Output -> g_Xd rows m (X1 rows 0..199, X2 rows 200..399), row stride BFl.
__global__ __launch_bounds__(256) void gemm_support(
    const float* __restrict__ src0, int st0, const float* __restrict__ src1,
    int split, int BFl, int colBase)
{
    __shared__ float As[8][64];
    __shared__ float Bs[8][256];
    const int m0 = blockIdx.y * 64;
    const int n0 = colBase + blockIdx.x * 256;
    const int t  = threadIdx.x;
    // B loads: 2 float4 per thread, per-thread source resolved once
    const int br  = t >> 5;            // 0..7
    const int bc0 = (t & 31) * 4;      // 0..124
    const float* bp[2]; int bst[2];
    #pragma unroll
    for (int q = 0; q < 2; q++) {
        int col = n0 + bc0 + 128*q;
        if (col < split) { bp[q] = src0 + col;           bst[q] = st0;  }
        else             { bp[q] = src1 + (col - split); bst[q] = 4096; }
    }
    const int ar = t & 63, ac = (t >> 6) * 2;   // A: float2 per thread
    const int tr = t >> 5, tc = t & 31;         // micro: rows tr*8.., cols tc*2+64j
    ull acc[8][4] = {};
    for (int k0 = 0; k0 < 200; k0 += 8) {
        float2 av = make_float2(0.f, 0.f);
        if (m0 + ar < 400) av = *(const float2*)&g_SS[(m0 + ar)*200 + k0 + ac];
        As[ac][ar] = av.x; As[ac + 1][ar] = av.y;
        #pragma unroll
        for (int q = 0; q < 2; q++)
            *(float4*)&Bs[br][bc0 + 128*q] = *(const float4*)&bp[q][(k0 + br)*bst[q]];
        __syncthreads();
        #pragma unroll
        for (int kk = 0; kk < 8; kk++) {
            ull bv[4], ap[8];
            #pragma unroll
            for (int j = 0; j < 4; j++) bv[j] = *(const ull*)&Bs[kk][tc*2 + 64*j];
            #pragma unroll
            for (int i = 0; i < 8; i++) { float a = As[kk][tr*8 + i]; ap[i] = pack2(a, a); }
            #pragma unroll
            for (int i = 0; i < 8; i++)
                #pragma unroll
                for (int j = 0; j < 4; j++) acc[i][j] = ffma2(ap[i], bv[j], acc[i][j]);
        }
        __syncthreads();
    }
    #pragma unroll
    for (int i = 0; i < 8; i++) {
        int m = m0 + tr*8 + i;
        if (m < 400) {
            #pragma unroll
            for (int j = 0; j < 4; j++)
                *(ull*)&g_Xd[m*BFl + n0 + tc*2 + 64*j] = acc[i][j];
        }
    }
}

// ---------------- GEMM 2: combine + epilogue ------------------------------
// One big GEMM: rows (n,b) = 12800, K = 3F (ks=0 virtual X0, ks=1,2 from g_Xd),
// N = 64 per block. MODE 0: sigmoid; o<64 -> g_rh = r*h, o>=64 -> g_u = u.
// MODE 1: tanh + GRU update of g_h[layer].
template <int MODE>
__global__ __launch_bounds__(256) void gemm_combine(
    int F, int inDim, const float* __restrict__ src0, int st0,
    const float* __restrict__ src1, int wOff, const float* __restrict__ bias,
    int layer)
{
    const int O = (MODE == 0) ? 128 : 64;
    __shared__ float As[8][128];
    __shared__ float Ws[8][64];
    const int BFl = F * 64, SEGl = 200 * BFl;
    const int n0 = blockIdx.y * 2;          // 2 nodes per block
    const int o0 = blockIdx.x * 64;
    const int t  = threadIdx.x;
    const int arow = t & 127;               // A-load row (0..127)
    const int an = arow >> 6, ab = arow & 63;
    const int akk = t >> 7;                 // kk = akk + 2q
    const int wr = t >> 5, wc = (t & 31) * 2;
    const int tr = t >> 4, tc = t & 15;     // micro: rows tr*8.., cols tc*2+32j
    ull acc[8][2] = {};
    const float* s0n = src0 + (n0 + an) * st0;
    const float* s1n = src1 + (n0 + an) * 4096;
    for (int ks = 0; ks < 3; ks++) {
        const float* Wseg = g_W + wOff + ks*F*O;
        const float* Xseg = g_Xd + (ks == 0 ? 0 : (ks - 1))*SEGl + (n0 + an)*BFl;
        for (int f0 = 0; f0 < F; f0 += 8) {
            #pragma unroll
            for (int q = 0; q < 4; q++) {
                int kk = akk + 2*q;
                int f  = f0 + kk;
                float v;
                if (ks == 0) v = (f < inDim) ? s0n[f*64 + ab] : s1n[(f - inDim)*64 + ab];
                else         v = Xseg[f*64 + ab];
                As[kk][arow] = v;
            }
            *(ull*)&Ws[wr][wc] = *(const ull*)&Wseg[(f0 + wr)*O + o0 + wc];
            __syncthreads();
            #pragma unroll
            for (int kk = 0; kk < 8; kk++) {
                ull b0 = *(const ull*)&Ws[kk][tc*2];
                ull b1 = *(const ull*)&Ws[kk][tc*2 + 32];
                #pragma unroll
                for (int i = 0; i < 8; i++) {
                    float a = As[kk][tr*8 + i];
                    ull ap = pack2(a, a);
                    acc[i][0] = ffma2(ap, b0, acc[i][0]);
                    acc[i][1] = ffma2(ap, b1, acc[i][1]);
                }
            }
            __syncthreads();
        }
    }
    float* hp = g_h[layer];
    #pragma unroll
    for (int i = 0; i < 8; i++) {
        int row = tr*8 + i;
        int n = n0 + (row >> 6), b = row & 63;
        #pragma unroll
        for (int j = 0; j < 2; j++) {
            int o = o0 + tc*2 + 32*j;
            float2 v = upk(acc[i][j]);
            float v0 = v.x + bias[o];
            float v1 = v.y + bias[o + 1];
            if (MODE == 0) {
                v0 = 1.f / (1.f + expf(-v0));
                v1 = 1.f / (1.f + expf(-v1));
                if (o0 == 0) {   // r gates -> rh
                    g_rh[n*4096 + o*64 + b]       = v0 * hp[n*4096 + o*64 + b];
                    g_rh[n*4096 + (o + 1)*64 + b] = v1 * hp[n*4096 + (o + 1)*64 + b];
                } else {         // u gates
                    g_u[n*4096 + (o - 64)*64 + b]     = v0;
                    g_u[n*4096 + (o - 64 + 1)*64 + b] = v1;
                }
            } else {
                float c0 = tanhf(v0), c1 = tanhf(v1);
                float u0 = g_u[n*4096 + o*64 + b];
                float u1 = g_u[n*4096 + (o + 1)*64 + b];
                float h0 = hp[n*4096 + o*64 + b];
                float h1 = hp[n*4096 + (o + 1)*64 + b];
                hp[n*4096 + o*64 + b]       = u0*h0 + (1.f - u0)*c0;
                hp[n*4096 + (o + 1)*64 + b] = u1*h1 + (1.f - u1)*c1;
            }
        }
    }
}

// ---------------- projection: out_t = h3 @ proj_W + proj_b -------------------
__global__ __launch_bounds__(256) void gemm_proj(const float* __restrict__ W,
                                                 const float* __restrict__ bias,
                                                 float* __restrict__ out, int t) {
    __shared__ float As[8][64];
    __shared__ float Ws[8][64];
    const int n  = blockIdx.y;
    const int o0 = blockIdx.x * 64;
    const int tt = threadIdx.x;
    const int tr = tt >> 4, tc = tt & 15;
    ull acc[4][2];
    #pragma unroll
    for (int i = 0; i < 4; i++) { acc[i][0] = 0ull; acc[i][1] = 0ull; }

    const int ar = tt & 63, ac = tt >> 6;
    const int wr = tt >> 5, wc = (tt & 31) * 2;
    const float* A = g_h[3] + n*4096;

    for (int k0 = 0; k0 < 64; k0 += 8) {
        As[ac][ar]     = A[(k0 + ac)*64 + ar];
        As[ac + 4][ar] = A[(k0 + ac + 4)*64 + ar];
        ull wv = 0ull;
        if (o0 + wc < 200) wv = *(const ull*)&W[(k0 + wr)*200 + o0 + wc];
        *(ull*)&Ws[wr][wc] = wv;
        __syncthreads();
        #pragma unroll
        for (int kk = 0; kk < 8; kk++) {
            ull ap[4];
            #pragma unroll
            for (int i = 0; i < 4; i++) { float a = As[kk][tr*4 + i]; ap[i] = pack2(a, a); }
            ull b0v = *(const ull*)&Ws[kk][tc*2];
            ull b1v = *(const ull*)&Ws[kk][tc*2 + 32];
            #pragma unroll
            for (int i = 0; i < 4; i++) {
                acc[i][0] = ffma2(ap[i], b0v, acc[i][0]);
                acc[i][1] = ffma2(ap[i], b1v, acc[i][1]);
            }
        }
        __syncthreads();
    }
    #pragma unroll
    for (int i = 0; i < 4; i++) {
        int b = tr*4 + i;
        #pragma unroll
        for (int j = 0; j < 2; j++) {
            int o = o0 + tc*2 + 32*j;
            if (o < 200) {
                float2 v = upk(acc[i][j]);
                v.x += bias[o];
                v.y += bias[o + 1];
                *(ull*)&out[b*480000 + t*40000 + n*200 + o] = pack2(v.x, v.y);
            }
        }
    }
}

// ---------------- host driver ----------------
extern "C" void kernel_launch(void* const* d_in, const int* in_sizes, int n_in,
                              void* d_out, int out_size) {
    const float* inputs  = (const float*)d_in[0];
    const float* support = (const float*)d_in[1];
    const float* projW   = (const float*)d_in[18];
    const float* projb   = (const float*)d_in[19];
    float* out = (float*)d_out;

    const float* Wsrc[2][4][2];
    const float* Bsrc[2][4][2];
    for (int s = 0; s < 2; s++) {
        int base = (s == 0) ? 2 : 10;
        Wsrc[s][0][0] = (const float*)d_in[base + 0];
        Bsrc[s][0][0] = (const float*)d_in[base + 1];
        Wsrc[s][0][1] = (const float*)d_in[base + 2];
        Bsrc[s][0][1] = (const float*)d_in[base + 3];
        const float* Wg = (const float*)d_in[base + 4];
        const float* Bg = (const float*)d_in[base + 5];
        const float* Wc = (const float*)d_in[base + 6];
        const float* Bc = (const float*)d_in[base + 7];
        for (int l = 1; l < 4; l++) {
            Wsrc[s][l][0] = Wg + (l - 1) * 384 * 128;
            Bsrc[s][l][0] = Bg + (l - 1) * 128;
            Wsrc[s][l][1] = Wc + (l - 1) * 384 * 64;
            Bsrc[s][l][1] = Bc + (l - 1) * 64;
        }
    }
    int wOff[2][4][2];
    for (int s = 0; s < 2; s++) {
        int base = s * 373248;
        wOff[s][0][0] = base;
        wOff[s][0][1] = base + 101376;
        for (int l = 1; l < 4; l++) {
            wOff[s][l][0] = base + 152064 + (l - 1) * 73728;
            wOff[s][l][1] = wOff[s][l][0] + 49152;
        }
    }

    // device symbol addresses usable as kernel args
    float* xin_p; cudaGetSymbolAddress((void**)&xin_p, g_xin);
    float* h_p;   cudaGetSymbolAddress((void**)&h_p,   g_h);
    float* rh_p;  cudaGetSymbolAddress((void**)&rh_p,  g_rh);

    // setup (runs every launch — deterministic, cheap)
    build_SS<<<400, 256>>>(support);
    zero_h<<<(NL*HSZ + 255) / 256, 256>>>();
    for (int s = 0; s < 2; s++)
        for (int l = 0; l < 4; l++) {
            int F = (l == 0) ? F0 : F1;
            reorder_W<<<(3*F*128 + 255) / 256, 256>>>(Wsrc[s][l][0], wOff[s][l][0], F, 128);
            reorder_W<<<(3*F*64  + 255) / 256, 256>>>(Wsrc[s][l][1], wOff[s][l][1], F, 64);
        }

    auto cell = [&](int s, int l, const float* l0src) {
        int F     = (l == 0) ? F0 : F1;
        int BFl   = F * 64;
        int inDim = F - 64;
        int split = inDim * 64;
        const float* src0 = (l == 0) ? xin_p : h_p + (l - 1) * HSZ;
        int st0 = (l == 0) ? 12800 : 4096;
        const float* hl = h_p + l * HSZ;

        if (l == 0) pack_l0_input<<<dim3(200, 7, 2), dim3(32, 8)>>>(l0src, 480000);

        // gate pass: diffuse all columns of [x, h], then gates (r->rh, u)
        gemm_support<<<dim3(BFl / 256, 7), 256>>>(src0, st0, hl, split, BFl, 0);
        gemm_combine<0><<<dim3(2, 100), 256>>>(F, inDim, src0, st0, hl,
                                               wOff[s][l][0], Bsrc[s][l][0], l);
        // candidate pass: re-diffuse only the state columns (now rh)
        gemm_support<<<dim3(16, 7), 256>>>(src0, st0, rh_p, split, BFl, split);
        gemm_combine<1><<<dim3(1, 100), 256>>>(F, inDim, src0, st0, rh_p,
                                               wOff[s][l][1], Bsrc[s][l][1], l);
    };

    // encoder
    for (int t = 0; t < NT; t++) {
        cell(0, 0, inputs + t * NNSQ);
        for (int l = 1; l < 4; l++) cell(0, l, nullptr);
    }
    // decoder
    for (int t = 0; t < NT; t++) {
        cell(1, 0, (t == 0) ? nullptr : out + (t - 1) * NNSQ);
        for (int l = 1; l < 4; l++) cell(1, l, nullptr);
        gemm_proj<<<dim3(4, 200), 256>>>(projW, projb, out, t);
    }
    (void)in_sizes; (void)n_in; (void)out_size;
}